// round 1
// baseline (speedup 1.0000x reference)
#include <cuda_runtime.h>
#include <math.h>

#define Bn 16384
#define Dn 1024
#define Kn 512
#define Ln 128
#define Hn 64

#define MT 128   // k-rows per CTA tile
#define BT 64    // b-cols per CTA tile
#define DK 16    // d-depth per SMEM stage

// ---- scratch (static device globals; no runtime allocation) ----
__device__ float g_phi[Kn * Dn];        // 2 MB
__device__ float g_phinorm[Kn];
__device__ float g_xnorm[Bn];
__device__ float g_block[Bn / BT];      // 256 per-block partial sums of log-lik

// ============================================================
// Kernel A: phi = ReLU(z @ W1 + b1) @ W2 + b2   (one block per k)
// also writes ||phi_k||^2
// ============================================================
__global__ __launch_bounds__(256) void phi_kernel(
    const float* __restrict__ z, const float* __restrict__ W1,
    const float* __restrict__ b1, const float* __restrict__ W2,
    const float* __restrict__ b2)
{
    __shared__ float zrow[Ln];
    __shared__ float hidden[Hn];
    __shared__ float red[256];

    const int k = blockIdx.x;
    const int t = threadIdx.x;

    if (t < Ln) zrow[t] = z[k * Ln + t];
    __syncthreads();

    if (t < Hn) {
        float acc = b1[t];
        #pragma unroll 8
        for (int l = 0; l < Ln; l++)
            acc = fmaf(zrow[l], W1[l * Hn + t], acc);
        hidden[t] = fmaxf(acc, 0.0f);
    }
    __syncthreads();

    const int d0 = t * 4;
    float4 acc = make_float4(b2[d0], b2[d0 + 1], b2[d0 + 2], b2[d0 + 3]);
    #pragma unroll 8
    for (int h = 0; h < Hn; h++) {
        const float hv = hidden[h];
        const float4 w = *reinterpret_cast<const float4*>(W2 + h * Dn + d0);
        acc.x = fmaf(hv, w.x, acc.x);
        acc.y = fmaf(hv, w.y, acc.y);
        acc.z = fmaf(hv, w.z, acc.z);
        acc.w = fmaf(hv, w.w, acc.w);
    }
    *reinterpret_cast<float4*>(g_phi + k * Dn + d0) = acc;

    red[t] = acc.x * acc.x + acc.y * acc.y + acc.z * acc.z + acc.w * acc.w;
    __syncthreads();
    for (int s = 128; s > 0; s >>= 1) {
        if (t < s) red[t] += red[t + s];
        __syncthreads();
    }
    if (t == 0) g_phinorm[k] = red[0];
}

// ============================================================
// Kernel B: ||x_b||^2 (one block per row b)
// ============================================================
__global__ __launch_bounds__(256) void xnorm_kernel(const float* __restrict__ x)
{
    __shared__ float red[256];
    const int b = blockIdx.x;
    const int t = threadIdx.x;
    const float4 v = *reinterpret_cast<const float4*>(x + b * Dn + t * 4);
    red[t] = v.x * v.x + v.y * v.y + v.z * v.z + v.w * v.w;
    __syncthreads();
    for (int s = 128; s > 0; s >>= 1) {
        if (t < s) red[t] += red[t + s];
        __syncthreads();
    }
    if (t == 0) g_xnorm[b] = red[0];
}

// ============================================================
// Kernel C: per CTA: 64 columns of x, full K=512 in 4 chunks of 128.
// S[k,b] = phi_k . x_b  via SMEM-tiled fp32 GEMM (8x4 microtiles),
// epilogue: colsum[b] += sum_k exp(-(||phi||^2 + ||x||^2 - 2 S)).
// Final: g_block[blk] = sum_b log(colsum[b]/K + eps)
// ============================================================
__global__ __launch_bounds__(256) void main_kernel(const float* __restrict__ x)
{
    __shared__ float phi_s[DK][MT + 4];   // +4 pad keeps 16B alignment, spreads banks
    __shared__ float x_s[DK][BT + 4];
    __shared__ float red[DK][BT];
    __shared__ float colsum[BT];

    const int t  = threadIdx.x;
    const int tx = t & 15;        // 16 b-groups of 4
    const int ty = t >> 4;        // 16 k-groups of 8
    const int b_base = blockIdx.x * BT;

    if (t < BT) colsum[t] = 0.0f;

    // per-thread xnorm for its 4 columns
    float xn[4];
    #pragma unroll
    for (int j = 0; j < 4; j++) xn[j] = g_xnorm[b_base + tx * 4 + j];

    for (int kc = 0; kc < Kn; kc += MT) {
        float acc[8][4];
        #pragma unroll
        for (int i = 0; i < 8; i++)
            #pragma unroll
            for (int j = 0; j < 4; j++) acc[i][j] = 0.0f;

        for (int d0 = 0; d0 < Dn; d0 += DK) {
            __syncthreads();
            // stage phi tile (128 x 16): 2 float4 per thread, transposed store
            #pragma unroll
            for (int r = 0; r < 2; r++) {
                const int q  = t + r * 256;       // 0..511
                const int kk = q >> 2;            // 0..127
                const int dd = (q & 3) * 4;
                const float4 v = *reinterpret_cast<const float4*>(
                    g_phi + (kc + kk) * Dn + d0 + dd);
                phi_s[dd + 0][kk] = v.x;
                phi_s[dd + 1][kk] = v.y;
                phi_s[dd + 2][kk] = v.z;
                phi_s[dd + 3][kk] = v.w;
            }
            {   // stage x tile (64 x 16): 1 float4 per thread
                const int bb = t >> 2;            // 0..63
                const int dd = (t & 3) * 4;
                const float4 v = *reinterpret_cast<const float4*>(
                    x + (b_base + bb) * Dn + d0 + dd);
                x_s[dd + 0][bb] = v.x;
                x_s[dd + 1][bb] = v.y;
                x_s[dd + 2][bb] = v.z;
                x_s[dd + 3][bb] = v.w;
            }
            __syncthreads();

            #pragma unroll
            for (int dd = 0; dd < DK; dd++) {
                const float4 xa = *reinterpret_cast<const float4*>(&x_s[dd][tx * 4]);
                const float4 p0 = *reinterpret_cast<const float4*>(&phi_s[dd][ty * 8]);
                const float4 p1 = *reinterpret_cast<const float4*>(&phi_s[dd][ty * 8 + 4]);
                const float pv[8] = {p0.x, p0.y, p0.z, p0.w, p1.x, p1.y, p1.z, p1.w};
                const float xv[4] = {xa.x, xa.y, xa.z, xa.w};
                #pragma unroll
                for (int i = 0; i < 8; i++)
                    #pragma unroll
                    for (int j = 0; j < 4; j++)
                        acc[i][j] = fmaf(pv[i], xv[j], acc[i][j]);
            }
        }

        // epilogue for this k-chunk: exp and partial K-sum
        float s[4] = {0.0f, 0.0f, 0.0f, 0.0f};
        #pragma unroll
        for (int i = 0; i < 8; i++) {
            const float pn = g_phinorm[kc + ty * 8 + i];
            #pragma unroll
            for (int j = 0; j < 4; j++) {
                const float sq = pn + xn[j] - 2.0f * acc[i][j];
                s[j] += __expf(-sq);
            }
        }
        __syncthreads();                       // red safe to overwrite
        #pragma unroll
        for (int j = 0; j < 4; j++) red[ty][tx * 4 + j] = s[j];
        __syncthreads();
        if (t < BT) {
            float tot = 0.0f;
            #pragma unroll
            for (int r = 0; r < DK; r++) tot += red[r][t];
            colsum[t] += tot;
        }
        __syncthreads();
    }

    // per-block log + partial sum over the 64 columns
    if (t < BT)
        red[0][t] = logf(colsum[t] * (1.0f / (float)Kn) + 1e-9f);
    __syncthreads();
    if (t == 0) {
        float tot = 0.0f;
        #pragma unroll 8
        for (int i = 0; i < BT; i++) tot += red[0][i];
        g_block[blockIdx.x] = tot;
    }
}

// ============================================================
// Kernel D: final reduce of 256 partials -> scalar mean
// ============================================================
__global__ __launch_bounds__(256) void final_kernel(float* __restrict__ out)
{
    __shared__ float red[256];
    const int t = threadIdx.x;
    red[t] = g_block[t];
    __syncthreads();
    for (int s = 128; s > 0; s >>= 1) {
        if (t < s) red[t] += red[t + s];
        __syncthreads();
    }
    if (t == 0) out[0] = red[0] * (1.0f / (float)Bn);
}

// ============================================================
extern "C" void kernel_launch(void* const* d_in, const int* in_sizes, int n_in,
                              void* d_out, int out_size)
{
    const float* x  = (const float*)d_in[0];
    const float* z  = (const float*)d_in[1];
    const float* W1 = (const float*)d_in[2];
    const float* b1 = (const float*)d_in[3];
    const float* W2 = (const float*)d_in[4];
    const float* b2 = (const float*)d_in[5];
    float* out = (float*)d_out;

    phi_kernel<<<Kn, 256>>>(z, W1, b1, W2, b2);
    xnorm_kernel<<<Bn, 256>>>(x);
    main_kernel<<<Bn / BT, 256>>>(x);
    final_kernel<<<1, 256>>>(out);
}

// round 3
// speedup vs baseline: 4.2849x; 4.2849x over previous
#include <cuda_runtime.h>
#include <cuda_bf16.h>
#include <math.h>
#include <cstdint>

#define Bn 16384
#define Dn 1024
#define Kn 512
#define Ln 128
#define Hn 64

#define MTILE 128      // k-rows per CTA
#define NTILE 128      // b-cols per CTA
#define DK    32       // bf16 depth per stage (64 bytes/row)
#define NCHUNK (Dn / DK)   // 32

// ---------------- scratch (static device globals) ----------------
__device__ __nv_bfloat16 g_phib[Kn * Dn];     // 1 MB
__device__ __nv_bfloat16 g_xb[Bn * Dn];       // 32 MB
__device__ float g_phinorm[Kn];
__device__ float g_xnorm[Bn];
__device__ float g_colsum[Bn];

// ---------------- helpers ----------------
__device__ __forceinline__ uint32_t smem_u32(const void* p) {
    uint32_t a;
    asm("{ .reg .u64 t; cvta.to.shared.u64 t, %1; cvt.u32.u64 %0, t; }" : "=r"(a) : "l"(p));
    return a;
}

// SW64-style swizzle: row stride 64B (32 bf16), 16B unit cg 0..3.
// offset (in bf16 elems) = row*32 + ((cg ^ ((row>>1)&3)) * 8)
__device__ __forceinline__ int swz(int row, int cg) {
    return row * 32 + (((cg ^ ((row >> 1) & 3))) << 3);
}

#define LDSM4(r0, r1, r2, r3, addr) \
    asm volatile("ldmatrix.sync.aligned.m8n8.x4.shared.b16 {%0,%1,%2,%3}, [%4];" \
                 : "=r"(r0), "=r"(r1), "=r"(r2), "=r"(r3) : "r"(addr))

#define MMA16816(d, a, b0, b1) \
    asm volatile("mma.sync.aligned.m16n8k16.row.col.f32.bf16.bf16.f32 " \
                 "{%0,%1,%2,%3}, {%4,%5,%6,%7}, {%8,%9}, {%0,%1,%2,%3};" \
                 : "+f"((d)[0]), "+f"((d)[1]), "+f"((d)[2]), "+f"((d)[3]) \
                 : "r"((a)[0]), "r"((a)[1]), "r"((a)[2]), "r"((a)[3]), \
                   "r"(b0), "r"(b1))

// ============================================================
// Kernel A: phi = ReLU(z@W1+b1)@W2+b2 ; fp32 norm + bf16 copy
// ============================================================
__global__ __launch_bounds__(256) void phi_kernel(
    const float* __restrict__ z, const float* __restrict__ W1,
    const float* __restrict__ b1, const float* __restrict__ W2,
    const float* __restrict__ b2)
{
    __shared__ float zrow[Ln];
    __shared__ float hidden[Hn];
    __shared__ float red[256];

    const int k = blockIdx.x;
    const int t = threadIdx.x;

    if (t < Ln) zrow[t] = z[k * Ln + t];
    __syncthreads();

    if (t < Hn) {
        float acc = b1[t];
        #pragma unroll 8
        for (int l = 0; l < Ln; l++)
            acc = fmaf(zrow[l], W1[l * Hn + t], acc);
        hidden[t] = fmaxf(acc, 0.0f);
    }
    __syncthreads();

    const int d0 = t * 4;
    float4 acc = make_float4(b2[d0], b2[d0 + 1], b2[d0 + 2], b2[d0 + 3]);
    #pragma unroll 8
    for (int h = 0; h < Hn; h++) {
        const float hv = hidden[h];
        const float4 w = *reinterpret_cast<const float4*>(W2 + h * Dn + d0);
        acc.x = fmaf(hv, w.x, acc.x);
        acc.y = fmaf(hv, w.y, acc.y);
        acc.z = fmaf(hv, w.z, acc.z);
        acc.w = fmaf(hv, w.w, acc.w);
    }
    __nv_bfloat162 p0 = __floats2bfloat162_rn(acc.x, acc.y);
    __nv_bfloat162 p1 = __floats2bfloat162_rn(acc.z, acc.w);
    uint2 packed;
    packed.x = *reinterpret_cast<uint32_t*>(&p0);
    packed.y = *reinterpret_cast<uint32_t*>(&p1);
    *reinterpret_cast<uint2*>(g_phib + k * Dn + d0) = packed;

    red[t] = acc.x * acc.x + acc.y * acc.y + acc.z * acc.z + acc.w * acc.w;
    __syncthreads();
    for (int s = 128; s > 0; s >>= 1) {
        if (t < s) red[t] += red[t + s];
        __syncthreads();
    }
    if (t == 0) g_phinorm[k] = red[0];
}

// ============================================================
// Kernel B: x -> bf16, ||x_b||^2, zero g_colsum
// ============================================================
__global__ __launch_bounds__(256) void xconv_kernel(const float* __restrict__ x)
{
    __shared__ float red[256];
    const int b = blockIdx.x;
    const int t = threadIdx.x;
    const float4 v = *reinterpret_cast<const float4*>(x + b * Dn + t * 4);
    __nv_bfloat162 p0 = __floats2bfloat162_rn(v.x, v.y);
    __nv_bfloat162 p1 = __floats2bfloat162_rn(v.z, v.w);
    uint2 packed;
    packed.x = *reinterpret_cast<uint32_t*>(&p0);
    packed.y = *reinterpret_cast<uint32_t*>(&p1);
    *reinterpret_cast<uint2*>(g_xb + b * Dn + t * 4) = packed;

    red[t] = v.x * v.x + v.y * v.y + v.z * v.z + v.w * v.w;
    __syncthreads();
    for (int s = 128; s > 0; s >>= 1) {
        if (t < s) red[t] += red[t + s];
        __syncthreads();
    }
    if (t == 0) {
        g_xnorm[b] = red[0];
        g_colsum[b] = 0.0f;
    }
}

// ============================================================
// Kernel C: bf16 mma.sync GEMM tile 128k x 128b + fused epilogue
// ============================================================
__global__ __launch_bounds__(256) void main_kernel()
{
    __shared__ __align__(16) __nv_bfloat16 As[2][MTILE * DK];   // 8KB/stage
    __shared__ __align__(16) __nv_bfloat16 Bs[2][NTILE * DK];   // 8KB/stage
    __shared__ float colsum[NTILE];

    const int t    = threadIdx.x;
    const int lane = t & 31;
    const int wid  = t >> 5;
    const int b_base = blockIdx.x * NTILE;
    const int k_base = blockIdx.y * MTILE;

    const int m_off = (wid & 1) * 64;    // warp m-tile (k components)
    const int n_off = (wid >> 1) * 32;   // warp n-tile (batch cols)

    if (t < NTILE) colsum[t] = 0.0f;

    // staging coords: thread t covers rows (t>>2) and (t>>2)+64, 16B unit cg=t&3
    const int srow = t >> 2;
    const int scg  = t & 3;
    const __nv_bfloat16* gA = g_phib + (uint64_t)k_base * Dn;
    const __nv_bfloat16* gB = g_xb   + (uint64_t)b_base * Dn;

    const uint32_t As0 = smem_u32(&As[0][0]);
    const uint32_t Bs0 = smem_u32(&Bs[0][0]);

    float acc[4][4][4];
    #pragma unroll
    for (int i = 0; i < 4; i++)
        #pragma unroll
        for (int j = 0; j < 4; j++)
            #pragma unroll
            for (int r = 0; r < 4; r++) acc[i][j][r] = 0.0f;

    // prologue: load chunk 0
    uint4 ra0 = *reinterpret_cast<const uint4*>(gA + srow * Dn + scg * 8);
    uint4 ra1 = *reinterpret_cast<const uint4*>(gA + (srow + 64) * Dn + scg * 8);
    uint4 rb0 = *reinterpret_cast<const uint4*>(gB + srow * Dn + scg * 8);
    uint4 rb1 = *reinterpret_cast<const uint4*>(gB + (srow + 64) * Dn + scg * 8);
    *reinterpret_cast<uint4*>(&As[0][swz(srow, scg)])      = ra0;
    *reinterpret_cast<uint4*>(&As[0][swz(srow + 64, scg)]) = ra1;
    *reinterpret_cast<uint4*>(&Bs[0][swz(srow, scg)])      = rb0;
    *reinterpret_cast<uint4*>(&Bs[0][swz(srow + 64, scg)]) = rb1;
    __syncthreads();

    for (int c = 0; c < NCHUNK; c++) {
        const int buf = c & 1;

        if (c + 1 < NCHUNK) {
            const int d0 = (c + 1) * DK + scg * 8;
            ra0 = *reinterpret_cast<const uint4*>(gA + srow * Dn + d0);
            ra1 = *reinterpret_cast<const uint4*>(gA + (srow + 64) * Dn + d0);
            rb0 = *reinterpret_cast<const uint4*>(gB + srow * Dn + d0);
            rb1 = *reinterpret_cast<const uint4*>(gB + (srow + 64) * Dn + d0);
        }

        const uint32_t Ab = As0 + (uint32_t)buf * (MTILE * DK * 2);
        const uint32_t Bb = Bs0 + (uint32_t)buf * (NTILE * DK * 2);

        #pragma unroll
        for (int ks = 0; ks < 2; ks++) {           // two k16 steps per DK=32
            uint32_t a[4][4];
            #pragma unroll
            for (int im = 0; im < 4; im++) {
                const int arow = m_off + im * 16 + (lane & 15);
                const int acg  = ks * 2 + (lane >> 4);
                LDSM4(a[im][0], a[im][1], a[im][2], a[im][3],
                      Ab + (uint32_t)(swz(arow, acg) * 2));
            }
            uint32_t b[8];
            #pragma unroll
            for (int in_ = 0; in_ < 2; in_++) {
                const int g    = lane >> 3;
                const int nrow = n_off + in_ * 16 + ((g >> 1) << 3) + (lane & 7);
                const int bcg  = ks * 2 + (g & 1);
                LDSM4(b[in_ * 4 + 0], b[in_ * 4 + 1], b[in_ * 4 + 2], b[in_ * 4 + 3],
                      Bb + (uint32_t)(swz(nrow, bcg) * 2));
            }
            #pragma unroll
            for (int im = 0; im < 4; im++)
                #pragma unroll
                for (int ing = 0; ing < 4; ing++)
                    MMA16816(acc[im][ing], a[im], b[ing * 2], b[ing * 2 + 1]);
        }

        if (c + 1 < NCHUNK) {
            const int nb = (c + 1) & 1;
            *reinterpret_cast<uint4*>(&As[nb][swz(srow, scg)])      = ra0;
            *reinterpret_cast<uint4*>(&As[nb][swz(srow + 64, scg)]) = ra1;
            *reinterpret_cast<uint4*>(&Bs[nb][swz(srow, scg)])      = rb0;
            *reinterpret_cast<uint4*>(&Bs[nb][swz(srow + 64, scg)]) = rb1;
        }
        __syncthreads();
    }

    // ---------------- fused epilogue ----------------
    // lane element map: acc[im][ing][r]:
    //   r0,r1: m = im*16 + (lane>>2),     n = ing*8 + (lane&3)*2 + {0,1}
    //   r2,r3: m = im*16 + (lane>>2) + 8, same n
    float pnl[4], pnh[4];
    #pragma unroll
    for (int im = 0; im < 4; im++) {
        pnl[im] = g_phinorm[k_base + m_off + im * 16 + (lane >> 2)];
        pnh[im] = g_phinorm[k_base + m_off + im * 16 + (lane >> 2) + 8];
    }
    float xnv[4][2];
    #pragma unroll
    for (int ing = 0; ing < 4; ing++)
        #pragma unroll
        for (int j = 0; j < 2; j++)
            xnv[ing][j] = g_xnorm[b_base + n_off + ing * 8 + (lane & 3) * 2 + j];

    float sn[4][2];
    #pragma unroll
    for (int ing = 0; ing < 4; ing++) { sn[ing][0] = 0.0f; sn[ing][1] = 0.0f; }

    #pragma unroll
    for (int im = 0; im < 4; im++) {
        #pragma unroll
        for (int ing = 0; ing < 4; ing++) {
            #pragma unroll
            for (int j = 0; j < 2; j++) {
                const float Sl = acc[im][ing][j];
                const float Sh = acc[im][ing][2 + j];
                sn[ing][j] += __expf(fmaf(2.0f, Sl, -(pnl[im] + xnv[ing][j])));
                sn[ing][j] += __expf(fmaf(2.0f, Sh, -(pnh[im] + xnv[ing][j])));
            }
        }
    }
    // reduce over the 8 m-lane groups (lanes differing in bits 2..4)
    #pragma unroll
    for (int off = 4; off < 32; off <<= 1)
        #pragma unroll
        for (int ing = 0; ing < 4; ing++)
            #pragma unroll
            for (int j = 0; j < 2; j++)
                sn[ing][j] += __shfl_xor_sync(0xffffffffu, sn[ing][j], off);

    if (lane < 4) {
        #pragma unroll
        for (int ing = 0; ing < 4; ing++)
            #pragma unroll
            for (int j = 0; j < 2; j++)
                atomicAdd(&colsum[n_off + ing * 8 + lane * 2 + j], sn[ing][j]);
    }
    __syncthreads();
    if (t < NTILE) atomicAdd(&g_colsum[b_base + t], colsum[t]);
}

// ============================================================
// Kernel D: mean_b log(colsum/K + eps)
// ============================================================
__global__ __launch_bounds__(1024) void final_kernel(float* __restrict__ out)
{
    __shared__ float red[32];
    const int t = threadIdx.x;
    float s = 0.0f;
    for (int i = t; i < Bn; i += 1024)
        s += logf(g_colsum[i] * (1.0f / (float)Kn) + 1e-9f);
    #pragma unroll
    for (int off = 16; off > 0; off >>= 1)
        s += __shfl_xor_sync(0xffffffffu, s, off);
    if ((t & 31) == 0) red[t >> 5] = s;
    __syncthreads();
    if (t < 32) {
        s = red[t];
        #pragma unroll
        for (int off = 16; off > 0; off >>= 1)
            s += __shfl_xor_sync(0xffffffffu, s, off);
        if (t == 0) out[0] = s * (1.0f / (float)Bn);
    }
}

// ============================================================
extern "C" void kernel_launch(void* const* d_in, const int* in_sizes, int n_in,
                              void* d_out, int out_size)
{
    const float* x  = (const float*)d_in[0];
    const float* z  = (const float*)d_in[1];
    const float* W1 = (const float*)d_in[2];
    const float* b1 = (const float*)d_in[3];
    const float* W2 = (const float*)d_in[4];
    const float* b2 = (const float*)d_in[5];
    float* out = (float*)d_out;

    phi_kernel<<<Kn, 256>>>(z, W1, b1, W2, b2);
    xconv_kernel<<<Bn, 256>>>(x);
    dim3 grid(Bn / NTILE, Kn / MTILE);   // (128, 4)
    main_kernel<<<grid, 256>>>();
    final_kernel<<<1, 1024>>>(out);
}

// round 4
// speedup vs baseline: 5.1538x; 1.2028x over previous
#include <cuda_runtime.h>
#include <cuda_bf16.h>
#include <math.h>
#include <cstdint>

#define Bn 16384
#define Dn 1024
#define Kn 512
#define Ln 128
#define Hn 64

#define MTILE 128      // k-rows per CTA
#define NTILE 128      // b-cols per CTA
#define DK    64       // bf16 depth per stage (128B rows, SW128 swizzle)
#define NCHUNK (Dn / DK)   // 16

#define L2E 1.4426950408889634f

// ---------------- scratch (static device globals) ----------------
__device__ __nv_bfloat16 g_phib[Kn * Dn];     // 1 MB
__device__ __nv_bfloat16 g_xb[Bn * Dn];       // 32 MB
__device__ float g_phinorm[Kn];
__device__ float g_xnorm[Bn];
__device__ float g_colsum[Bn];

// ---------------- helpers ----------------
__device__ __forceinline__ uint32_t smem_u32(const void* p) {
    uint32_t a;
    asm("{ .reg .u64 t; cvta.to.shared.u64 t, %1; cvt.u32.u64 %0, t; }" : "=r"(a) : "l"(p));
    return a;
}

#define LDSM4(r0, r1, r2, r3, addr) \
    asm volatile("ldmatrix.sync.aligned.m8n8.x4.shared.b16 {%0,%1,%2,%3}, [%4];" \
                 : "=r"(r0), "=r"(r1), "=r"(r2), "=r"(r3) : "r"(addr))

#define MMA16816(d, a, b0, b1) \
    asm volatile("mma.sync.aligned.m16n8k16.row.col.f32.bf16.bf16.f32 " \
                 "{%0,%1,%2,%3}, {%4,%5,%6,%7}, {%8,%9}, {%0,%1,%2,%3};" \
                 : "+f"((d)[0]), "+f"((d)[1]), "+f"((d)[2]), "+f"((d)[3]) \
                 : "r"((a)[0]), "r"((a)[1]), "r"((a)[2]), "r"((a)[3]), \
                   "r"(b0), "r"(b1))

#define CP16(dst, src) \
    asm volatile("cp.async.cg.shared.global [%0], [%1], 16;" :: "r"(dst), "l"(src))
#define CP_COMMIT() asm volatile("cp.async.commit_group;" ::: "memory")
#define CP_WAIT0()  asm volatile("cp.async.wait_group 0;" ::: "memory")

// fast 2^t for t <= ~0 (clamped): FFMA-only, no MUFU.
// range-reduce by rint -> f in [-0.5, 0.5], degree-4 Taylor (max rel err ~4e-5)
__device__ __forceinline__ float exp2_fast(float t) {
    t = fmaxf(t, -126.0f);
    const int   i  = __float2int_rn(t);
    const float f  = t - (float)i;
    float p = fmaf(0.0096181291f, f, 0.0555041087f);
    p = fmaf(p, f, 0.2402265069f);
    p = fmaf(p, f, 0.6931471806f);
    p = fmaf(p, f, 1.0f);
    return p * __int_as_float((i + 127) << 23);
}

// ============================================================
// Kernel A: phi = ReLU(z@W1+b1)@W2+b2 ; fp32 norm + bf16 copy
// ============================================================
__global__ __launch_bounds__(256) void phi_kernel(
    const float* __restrict__ z, const float* __restrict__ W1,
    const float* __restrict__ b1, const float* __restrict__ W2,
    const float* __restrict__ b2)
{
    __shared__ float zrow[Ln];
    __shared__ float hidden[Hn];
    __shared__ float red[256];

    const int k = blockIdx.x;
    const int t = threadIdx.x;

    if (t < Ln) zrow[t] = z[k * Ln + t];
    __syncthreads();

    if (t < Hn) {
        float acc = b1[t];
        #pragma unroll 8
        for (int l = 0; l < Ln; l++)
            acc = fmaf(zrow[l], W1[l * Hn + t], acc);
        hidden[t] = fmaxf(acc, 0.0f);
    }
    __syncthreads();

    const int d0 = t * 4;
    float4 acc = make_float4(b2[d0], b2[d0 + 1], b2[d0 + 2], b2[d0 + 3]);
    #pragma unroll 8
    for (int h = 0; h < Hn; h++) {
        const float hv = hidden[h];
        const float4 w = *reinterpret_cast<const float4*>(W2 + h * Dn + d0);
        acc.x = fmaf(hv, w.x, acc.x);
        acc.y = fmaf(hv, w.y, acc.y);
        acc.z = fmaf(hv, w.z, acc.z);
        acc.w = fmaf(hv, w.w, acc.w);
    }
    __nv_bfloat162 p0 = __floats2bfloat162_rn(acc.x, acc.y);
    __nv_bfloat162 p1 = __floats2bfloat162_rn(acc.z, acc.w);
    uint2 packed;
    packed.x = *reinterpret_cast<uint32_t*>(&p0);
    packed.y = *reinterpret_cast<uint32_t*>(&p1);
    *reinterpret_cast<uint2*>(g_phib + k * Dn + d0) = packed;

    red[t] = acc.x * acc.x + acc.y * acc.y + acc.z * acc.z + acc.w * acc.w;
    __syncthreads();
    for (int s = 128; s > 0; s >>= 1) {
        if (t < s) red[t] += red[t + s];
        __syncthreads();
    }
    if (t == 0) g_phinorm[k] = red[0];
}

// ============================================================
// Kernel B: x -> bf16, ||x_b||^2, zero g_colsum and d_out
// ============================================================
__global__ __launch_bounds__(256) void xconv_kernel(const float* __restrict__ x,
                                                    float* __restrict__ out)
{
    __shared__ float red[256];
    const int b = blockIdx.x;
    const int t = threadIdx.x;
    const float4 v = *reinterpret_cast<const float4*>(x + b * Dn + t * 4);
    __nv_bfloat162 p0 = __floats2bfloat162_rn(v.x, v.y);
    __nv_bfloat162 p1 = __floats2bfloat162_rn(v.z, v.w);
    uint2 packed;
    packed.x = *reinterpret_cast<uint32_t*>(&p0);
    packed.y = *reinterpret_cast<uint32_t*>(&p1);
    *reinterpret_cast<uint2*>(g_xb + b * Dn + t * 4) = packed;

    red[t] = v.x * v.x + v.y * v.y + v.z * v.z + v.w * v.w;
    __syncthreads();
    for (int s = 128; s > 0; s >>= 1) {
        if (t < s) red[t] += red[t + s];
        __syncthreads();
    }
    if (t == 0) {
        g_xnorm[b] = red[0];
        g_colsum[b] = 0.0f;
        if (b == 0) out[0] = 0.0f;
    }
}

// ============================================================
// Kernel C: bf16 mma.sync GEMM 128x128 tile, cp.async pipeline,
//           fused FFMA-exp epilogue -> g_colsum atomics
// ============================================================
__global__ __launch_bounds__(256, 2) void main_kernel()
{
    extern __shared__ char smem[];
    const uint32_t Abase = smem_u32(smem);            // 2 stages x 16KB
    const uint32_t Bbase = Abase + 32768;             // 2 stages x 16KB

    const int t    = threadIdx.x;
    const int lane = t & 31;
    const int wid  = t >> 5;
    const int b_base = blockIdx.x * NTILE;
    const int k_base = blockIdx.y * MTILE;

    const int m_off = (wid & 1) * 64;
    const int n_off = (wid >> 1) * 32;

    const __nv_bfloat16* gA = g_phib + (uint64_t)k_base * Dn;
    const __nv_bfloat16* gB = g_xb   + (uint64_t)b_base * Dn;

    // staging map: 4 16B-units per array per thread
    int   srow[4];
    int   sgo[4];            // global element offset within row chunk (cg*8)
    uint32_t soff[4];        // swizzled byte offset within a stage
    #pragma unroll
    for (int i = 0; i < 4; i++) {
        const int u = t + i * 256;
        const int row = u >> 3;
        const int cg  = u & 7;
        srow[i] = row;
        sgo[i]  = cg * 8;
        soff[i] = (uint32_t)(row * 128 + ((cg ^ (row & 7)) << 4));
    }

    float acc[4][4][4];
    #pragma unroll
    for (int i = 0; i < 4; i++)
        #pragma unroll
        for (int j = 0; j < 4; j++)
            #pragma unroll
            for (int r = 0; r < 4; r++) acc[i][j][r] = 0.0f;

    // ---- prologue: load chunk 0 into stage 0 ----
    #pragma unroll
    for (int i = 0; i < 4; i++) {
        CP16(Abase + soff[i], gA + srow[i] * Dn + sgo[i]);
        CP16(Bbase + soff[i], gB + srow[i] * Dn + sgo[i]);
    }
    CP_COMMIT();

    for (int c = 0; c < NCHUNK; c++) {
        const int buf = c & 1;
        CP_WAIT0();
        __syncthreads();

        if (c + 1 < NCHUNK) {
            const int nb = (c + 1) & 1;
            const int d0 = (c + 1) * DK;
            #pragma unroll
            for (int i = 0; i < 4; i++) {
                CP16(Abase + (uint32_t)nb * 16384u + soff[i], gA + srow[i] * Dn + d0 + sgo[i]);
                CP16(Bbase + (uint32_t)nb * 16384u + soff[i], gB + srow[i] * Dn + d0 + sgo[i]);
            }
            CP_COMMIT();
        }

        const uint32_t Ab = Abase + (uint32_t)buf * 16384u;
        const uint32_t Bb = Bbase + (uint32_t)buf * 16384u;

        #pragma unroll
        for (int ks = 0; ks < 4; ks++) {      // four k16 steps per DK=64
            uint32_t a[4][4];
            #pragma unroll
            for (int im = 0; im < 4; im++) {
                const int arow = m_off + im * 16 + (lane & 15);
                const int acg  = ks * 2 + (lane >> 4);
                LDSM4(a[im][0], a[im][1], a[im][2], a[im][3],
                      Ab + (uint32_t)(arow * 128 + ((acg ^ (arow & 7)) << 4)));
            }
            uint32_t b[8];
            #pragma unroll
            for (int in_ = 0; in_ < 2; in_++) {
                const int g    = lane >> 3;
                const int nrow = n_off + in_ * 16 + ((g >> 1) << 3) + (lane & 7);
                const int bcg  = ks * 2 + (g & 1);
                LDSM4(b[in_ * 4 + 0], b[in_ * 4 + 1], b[in_ * 4 + 2], b[in_ * 4 + 3],
                      Bb + (uint32_t)(nrow * 128 + ((bcg ^ (nrow & 7)) << 4)));
            }
            #pragma unroll
            for (int im = 0; im < 4; im++)
                #pragma unroll
                for (int ing = 0; ing < 4; ing++)
                    MMA16816(acc[im][ing], a[im], b[ing * 2], b[ing * 2 + 1]);
        }
    }

    // ---------------- fused epilogue (FFMA exp) ----------------
    // acc[im][ing][r]: r0,r1: m = im*16 + (lane>>2),   n = ing*8 + (lane&3)*2 + {0,1}
    //                  r2,r3: m = im*16 + (lane>>2)+8, same n
    float pnl[4], pnh[4];
    #pragma unroll
    for (int im = 0; im < 4; im++) {
        pnl[im] = g_phinorm[k_base + m_off + im * 16 + (lane >> 2)] * L2E;
        pnh[im] = g_phinorm[k_base + m_off + im * 16 + (lane >> 2) + 8] * L2E;
    }
    float xnv[4][2];
    #pragma unroll
    for (int ing = 0; ing < 4; ing++)
        #pragma unroll
        for (int j = 0; j < 2; j++)
            xnv[ing][j] = g_xnorm[b_base + n_off + ing * 8 + (lane & 3) * 2 + j] * L2E;

    float sn[4][2];
    #pragma unroll
    for (int ing = 0; ing < 4; ing++) { sn[ing][0] = 0.0f; sn[ing][1] = 0.0f; }

    #pragma unroll
    for (int im = 0; im < 4; im++) {
        #pragma unroll
        for (int ing = 0; ing < 4; ing++) {
            #pragma unroll
            for (int j = 0; j < 2; j++) {
                const float c1 = pnl[im] + xnv[ing][j];
                const float c2 = pnh[im] + xnv[ing][j];
                sn[ing][j] += exp2_fast(fmaf(2.0f * L2E, acc[im][ing][j],     -c1));
                sn[ing][j] += exp2_fast(fmaf(2.0f * L2E, acc[im][ing][2 + j], -c2));
            }
        }
    }
    // reduce over the 8 m-lane groups (lane bits 2..4)
    #pragma unroll
    for (int off = 4; off < 32; off <<= 1)
        #pragma unroll
        for (int ing = 0; ing < 4; ing++)
            #pragma unroll
            for (int j = 0; j < 2; j++)
                sn[ing][j] += __shfl_xor_sync(0xffffffffu, sn[ing][j], off);

    if (lane < 4) {
        #pragma unroll
        for (int ing = 0; ing < 4; ing++)
            #pragma unroll
            for (int j = 0; j < 2; j++)
                atomicAdd(&g_colsum[b_base + n_off + ing * 8 + lane * 2 + j], sn[ing][j]);
    }
}

// ============================================================
// Kernel D: parallel mean_b log(colsum/K + eps) -> atomicAdd out
// ============================================================
__global__ __launch_bounds__(256) void final_kernel(float* __restrict__ out)
{
    __shared__ float red[8];
    const int t = threadIdx.x;
    const int gid = blockIdx.x * 256 + t;
    float s = __logf(g_colsum[gid] * (1.0f / (float)Kn) + 1e-9f) * (1.0f / (float)Bn);
    #pragma unroll
    for (int off = 16; off > 0; off >>= 1)
        s += __shfl_xor_sync(0xffffffffu, s, off);
    if ((t & 31) == 0) red[t >> 5] = s;
    __syncthreads();
    if (t < 8) {
        s = red[t];
        #pragma unroll
        for (int off = 4; off > 0; off >>= 1)
            s += __shfl_xor_sync(0xffffffffu, s, off);
        if (t == 0) atomicAdd(out, s);
    }
}

// ============================================================
extern "C" void kernel_launch(void* const* d_in, const int* in_sizes, int n_in,
                              void* d_out, int out_size)
{
    const float* x  = (const float*)d_in[0];
    const float* z  = (const float*)d_in[1];
    const float* W1 = (const float*)d_in[2];
    const float* b1 = (const float*)d_in[3];
    const float* W2 = (const float*)d_in[4];
    const float* b2 = (const float*)d_in[5];
    float* out = (float*)d_out;

    static int smem_set = 0;
    if (!smem_set) {
        cudaFuncSetAttribute(main_kernel, cudaFuncAttributeMaxDynamicSharedMemorySize, 65536);
        smem_set = 1;
    }

    phi_kernel<<<Kn, 256>>>(z, W1, b1, W2, b2);
    xconv_kernel<<<Bn, 256>>>(x, out);
    dim3 grid(Bn / NTILE, Kn / MTILE);   // (128, 4)
    main_kernel<<<grid, 256, 65536>>>();
    final_kernel<<<Bn / 256, 256>>>(out);
}